// round 9
// baseline (speedup 1.0000x reference)
#include <cuda_runtime.h>
#include <cuda_bf16.h>

// Trilinear scatter-add (Gridding).
// L2-resident chunked zero+scatter pipeline + vector reductions.
//
// Converged findings (R1-R7):
//  - Bottleneck: chip-shared L2/LTS throughput (atomic ALU); total time ==
//    sum of scatter-kernel times (~12.9us/chunk x 8 = 103us).
//  - bz%4 red encoding (v2 / padded-v4 / 2x scalar) is op-minimal: 5 ops/pt.
//  - 8 chunks, 1 pt/thread grid-stride, 256-thr blocks, rate-limit 3,
//    low-priority zero stream = champion config (102.5us).
//  - R8: zero via cudaMemsetAsync graph nodes instead of an SM kernel ->
//    zeros stop competing for SM issue/occupancy during the overlap window.
//    Coverage: memset chunk c = elements [c*out/C,(c+1)*out/C); since
//    floor((c+1)B/C)*G3 <= (c+1)*out/C, memsets 0..c (sequential) always
//    cover scatter chunk c's batches, for any B,C.
//
// All shape parameters derived on-device from scale/out_size.

__device__ __forceinline__ void get_dims(const int* __restrict__ scale_p,
                                         int out_size, int npts,
                                         int& s, int& G, int& G2, int& G3,
                                         int& B, int& N) {
    const int scale = *scale_p;
    s = scale >> 1;
    G = 2 * s;
    G2 = G * G;
    G3 = G2 * G;
    B = out_size / G3;
    N = npts / B;
}

__device__ __forceinline__ void red2(float* p, float a, float b) {
    asm volatile("red.global.add.v2.f32 [%0], {%1, %2};"
                 :: "l"(p), "f"(a), "f"(b) : "memory");
}

__device__ __forceinline__ void red4(float* p, float a, float b, float c, float d) {
    asm volatile("red.global.add.v4.f32 [%0], {%1, %2, %3, %4};"
                 :: "l"(p), "f"(a), "f"(b), "f"(c), "f"(d) : "memory");
}

// Scatter the points of batches [c*B/C, (c+1)*B/C).
__global__ void gridding_scatter_chunk(const float* __restrict__ pts,
                                       const int* __restrict__ scale_p,
                                       float* __restrict__ out,
                                       int npts, int out_size, int c, int C) {
    int s, G, G2, G3, B, N;
    get_dims(scale_p, out_size, npts, s, G, G2, G3, B, N);

    const int b0 = (int)((long long)c * B / C);
    const int b1 = (int)((long long)(c + 1) * B / C);
    const int i_lo = b0 * N;
    const int i_hi = b1 * N;

    const float fs = (float)s;
    const int stride = gridDim.x * blockDim.x;

    for (int i = i_lo + blockIdx.x * blockDim.x + threadIdx.x;
         i < i_hi; i += stride) {
        const int b = b0 + (i - i_lo) / N;

        const float px = pts[3 * i + 0] * fs;
        const float py = pts[3 * i + 1] * fs;
        const float pz = pts[3 * i + 2] * fs;

        // Reference drops points whose scaled coords sum to exactly 0.
        const float m = (((px + py) + pz) != 0.0f) ? 1.0f : 0.0f;

        const float lx = floorf(px);
        const float ly = floorf(py);
        const float lz = floorf(pz);
        const float fx = px - lx;
        const float fy = py - ly;
        const float fz = pz - lz;

        const int bx = (int)lx + s;
        const int by = (int)ly + s;
        const int bz = (int)lz + s;

        const float wx0 = (1.0f - fx) * m;
        const float wx1 = fx * m;
        const float wy0 = 1.0f - fy;
        const float wy1 = fy;
        const float wz0 = 1.0f - fz;
        const float wz1 = fz;

        const float w00 = wx0 * wy0;
        const float w01 = wx0 * wy1;
        const float w10 = wx1 * wy0;
        const float w11 = wx1 * wy1;

        const float a0 = w00 * wz0, c0 = w00 * wz1;
        const float a1 = w01 * wz0, c1 = w01 * wz1;
        const float a2 = w10 * wz0, c2 = w10 * wz1;
        const float a3 = w11 * wz0, c3 = w11 * wz1;

        float* p0 = out + (size_t)b * G3 + ((size_t)bx * G + by) * G + bz;
        float* p1 = p0 + G;
        float* p2 = p0 + G2;
        float* p3 = p2 + G;

        const int off = bz & 3;
        if (off == 3) {
            // Pair straddles a 16B window: 2 scalar reds per corner.
            atomicAdd(p0, a0); atomicAdd(p0 + 1, c0);
            atomicAdd(p1, a1); atomicAdd(p1 + 1, c1);
            atomicAdd(p2, a2); atomicAdd(p2 + 1, c2);
            atomicAdd(p3, a3); atomicAdd(p3 + 1, c3);
        } else if (off == 1) {
            // Odd start inside the window: one v4 with zero padding.
            red4(p0 - 1, 0.f, a0, c0, 0.f);
            red4(p1 - 1, 0.f, a1, c1, 0.f);
            red4(p2 - 1, 0.f, a2, c2, 0.f);
            red4(p3 - 1, 0.f, a3, c3, 0.f);
        } else {
            // bz even: naturally 8B-aligned pair, one v2.
            red2(p0, a0, c0);
            red2(p1, a1, c1);
            red2(p2, a2, c2);
            red2(p3, a3, c3);
        }
    }
}

static const int kChunks = 8;

extern "C" void kernel_launch(void* const* d_in, const int* in_sizes, int n_in,
                              void* d_out, int out_size) {
    const float* pts = (const float*)d_in[0];
    const int* scale_p = (const int*)d_in[1];
    float* out = (float*)d_out;

    const int npts = in_sizes[0] / 3;

    // One-time creation of helper streams + events (no device memory).
    static cudaStream_t sZ = nullptr;   // zeroing stream (low priority)
    static cudaStream_t sS = nullptr;   // second scatter stream (odd chunks)
    static cudaEvent_t evFork = nullptr;
    static cudaEvent_t evZ[kChunks];
    static cudaEvent_t evS[kChunks];
    if (sZ == nullptr) {
        int prLo = 0, prHi = 0;
        cudaDeviceGetStreamPriorityRange(&prLo, &prHi);  // prLo = lowest prio
        cudaStreamCreateWithPriority(&sZ, cudaStreamNonBlocking, prLo);
        cudaStreamCreateWithFlags(&sS, cudaStreamNonBlocking);
        cudaEventCreateWithFlags(&evFork, cudaEventDisableTiming);
        for (int c = 0; c < kChunks; c++) {
            cudaEventCreateWithFlags(&evZ[c], cudaEventDisableTiming);
            cudaEventCreateWithFlags(&evS[c], cudaEventDisableTiming);
        }
    }

    const int threads = 256;
    int blocksS = (npts / kChunks + threads - 1) / threads + 2;

    // Fork side streams off the capture stream.
    cudaEventRecord(evFork, 0);
    cudaStreamWaitEvent(sZ, evFork, 0);
    cudaStreamWaitEvent(sS, evFork, 0);

    for (int c = 0; c < kChunks; c++) {
        // Rate-limit zeros: keep at most ~3 chunks hot in L2.
        if (c >= 3) cudaStreamWaitEvent(sZ, evS[c - 3], 0);

        // Zero chunk c via a memset node (no SM involvement). Element range
        // [c*out/C, (c+1)*out/C); sequential on sZ, so evZ[c] implies all
        // memsets 0..c done, which covers scatter chunk c's batch range.
        const size_t e_lo = (size_t)c * (size_t)out_size / kChunks;
        const size_t e_hi = (size_t)(c + 1) * (size_t)out_size / kChunks;
        cudaMemsetAsync(out + e_lo, 0, (e_hi - e_lo) * sizeof(float), sZ);
        cudaEventRecord(evZ[c], sZ);

        // Scatter chunk c once its zeros are in L2. Even chunks on the
        // capture stream, odd chunks on the second stream.
        cudaStream_t st = (c & 1) ? sS : (cudaStream_t)0;
        cudaStreamWaitEvent(st, evZ[c], 0);
        gridding_scatter_chunk<<<blocksS, threads, 0, st>>>(
            pts, scale_p, out, npts, out_size, c, kChunks);
        cudaEventRecord(evS[c], st);
    }

    // Join everything back into the capture stream.
    cudaStreamWaitEvent(0, evS[kChunks - 1], 0);
}